// round 16
// baseline (speedup 1.0000x reference)
#include <cuda_runtime.h>
#include <cstdint>

#define SS 2048
#define RR 384

typedef unsigned long long ull;

// ---- device scratch (no allocs allowed) ----
__device__ float g_kv[RR * 16 * SS];     // [r][c][s]; c: 0-7 = k, 8-15 = v
__device__ float g_maskT[RR * SS];       // transposed mask [r][s]
__device__ float g_qpart[RR * 16 * 68];  // per-(r, s-block) partials
__device__ float g_o[RR * 64];           // attention output per r  [h*8+c]
__device__ float2 g_stats[RR * SS];      // per-row (mu, rstd), [r][s] layout
// LN-folded weights
__device__ float g_AW[16 * 64];          // [c][d] = g[d]*Wkv[d][c]
__device__ float g_S1kv[16];
__device__ float g_bkv[16];
__device__ float g_GW[64 * 64];          // [j][d] = g[d]*Wg[d][j]
__device__ float g_S1g[64];
__device__ float g_bG[64];               // bg[j] + sum_d b[d]*Wg[d][j]
__device__ float g_WoT[64 * 64];         // [d][j] = Wo[j][d]
// pre-packed tf32 B-fragments for kernelC  (chunk c holds k-steps 2c, 2c+1)
__device__ uint4 g_BP1[1024];            // gate GEMM:  [c][n*32+lane]
__device__ uint4 g_BP2[1024];            // out  GEMM:  [c][n*32+lane]

// ---- packed fp32x2 helpers ----
__device__ __forceinline__ ull ffma2(ull a, ull b, ull c) {
    ull d;
    asm("fma.rn.f32x2 %0, %1, %2, %3;" : "=l"(d) : "l"(a), "l"(b), "l"(c));
    return d;
}
__device__ __forceinline__ float2 upk(ull v) {
    float2 f; asm("mov.b64 {%0,%1}, %2;" : "=f"(f.x), "=f"(f.y) : "l"(v)); return f;
}
__device__ __forceinline__ ull pk2(float lo, float hi) {
    ull r; asm("mov.b64 %0, {%1,%2};" : "=l"(r) : "f"(lo), "f"(hi)); return r;
}

// ---- warp MMA helpers (arch-legal on compute_103) ----
__device__ __forceinline__ uint32_t f2tf32(float x) {
    uint32_t r; asm("cvt.rna.tf32.f32 %0, %1;" : "=r"(r) : "f"(x)); return r;
}
__device__ __forceinline__ void mma_tf32(float* d, const uint32_t* a,
                                         uint32_t b0, uint32_t b1) {
    asm volatile(
        "mma.sync.aligned.m16n8k8.row.col.f32.tf32.tf32.f32 "
        "{%0,%1,%2,%3}, {%4,%5,%6,%7}, {%8,%9}, {%0,%1,%2,%3};"
        : "+f"(d[0]), "+f"(d[1]), "+f"(d[2]), "+f"(d[3])
        : "r"(a[0]), "r"(a[1]), "r"(a[2]), "r"(a[3]), "r"(b0), "r"(b1));
}

// ---------------------------------------------------------------------------
// Kernel DP: mask transpose (blocks 0..767) + weight folding/packing (768)
// ---------------------------------------------------------------------------
__global__ __launch_bounds__(256) void kernelDP(
    const float* __restrict__ Mmask,
    const float* __restrict__ lng, const float* __restrict__ lnb,
    const float* __restrict__ Wk, const float* __restrict__ Wv,
    const float* __restrict__ Wg, const float* __restrict__ bg,
    const float* __restrict__ Wo)
{
    const int tid = threadIdx.x;
    if (blockIdx.x < 768) {
        __shared__ float t[32][33];
        const int bx = blockIdx.x % 12, by = blockIdx.x / 12;
        const int tx = tid & 31, ty = tid >> 5;
        const int r0 = bx * 32, s0 = by * 32;
        #pragma unroll
        for (int k = 0; k < 32; k += 8)
            t[ty + k][tx] = Mmask[(s0 + ty + k) * RR + r0 + tx];
        __syncthreads();
        #pragma unroll
        for (int k = 0; k < 32; k += 8)
            g_maskT[(r0 + ty + k) * SS + s0 + tx] = t[tx][ty + k];
    } else {
        for (int i = tid; i < 16 * 64; i += 256) {
            int c = i >> 6, d = i & 63;
            float w = (c < 8) ? Wk[d * 8 + c] : Wv[d * 8 + c - 8];
            g_AW[i] = lng[d] * w;
        }
        for (int i = tid; i < 64 * 64; i += 256) {
            int a = i >> 6, b = i & 63;
            g_GW[i]  = lng[b] * Wg[b * 64 + a];   // [j=a][d=b]
            g_WoT[i] = Wo[b * 64 + a];            // [d=a][j=b]
        }
        // pre-packed tf32 B fragments for kernelC
        for (int i = tid; i < 1024; i += 256) {
            int c = i >> 8, rem = i & 255;
            int col = rem >> 2, tg = rem & 3;
            int d0 = 16 * c + tg, d1 = d0 + 4, d2 = d0 + 8, d3 = d0 + 12;
            uint4 v1, v2;
            v1.x = f2tf32(lng[d0] * Wg[d0 * 64 + col]);
            v1.y = f2tf32(lng[d1] * Wg[d1 * 64 + col]);
            v1.z = f2tf32(lng[d2] * Wg[d2 * 64 + col]);
            v1.w = f2tf32(lng[d3] * Wg[d3 * 64 + col]);
            g_BP1[i] = v1;
            v2.x = f2tf32(Wo[d0 * 64 + col]);
            v2.y = f2tf32(Wo[d1 * 64 + col]);
            v2.z = f2tf32(Wo[d2 * 64 + col]);
            v2.w = f2tf32(Wo[d3 * 64 + col]);
            g_BP2[i] = v2;
        }
        __syncthreads();
        if (tid < 16) {
            float s1 = 0.f, bb = 0.f;
            for (int d = 0; d < 64; ++d) {
                s1 += g_AW[tid * 64 + d];
                float w = (tid < 8) ? Wk[d * 8 + tid] : Wv[d * 8 + tid - 8];
                bb += lnb[d] * w;
            }
            g_S1kv[tid] = s1; g_bkv[tid] = bb;
        }
        if (tid >= 64 && tid < 128) {
            int j = tid - 64;
            float s1 = 0.f, bb = 0.f;
            for (int d = 0; d < 64; ++d) {
                s1 += g_GW[j * 64 + d];
                bb += lnb[d] * Wg[d * 64 + j];
            }
            g_S1g[j] = s1; g_bG[j] = bg[j] + bb;
        }
    }
}

// ---------------------------------------------------------------------------
// Kernel A: rows-in-lanes LN (folded) + k/v projection + masked-q partials
// + stores per-row (mu, rstd) to g_stats[r][s] for kernelC
// ---------------------------------------------------------------------------
__global__ __launch_bounds__(128) void kernelA(const float* __restrict__ M) {
    __shared__ __align__(16) float stage[4][32][68];
    __shared__ __align__(16) float sAW[16][68];
    __shared__ float sS1[16], sbk[16];
    __shared__ float sQ[4][68];
    const int tid = threadIdx.x, w = tid >> 5, t = tid & 31;
    const int r = blockIdx.y;
    const int srow = blockIdx.x * 128 + w * 32;

    for (int i = tid; i < 16 * 64; i += 128) { int c = i >> 6, d = i & 63; sAW[c][d] = g_AW[i]; }
    if (tid < 16) { sS1[tid] = g_S1kv[tid]; sbk[tid] = g_bkv[tid]; }
    __syncthreads();

    const int cr = t >> 4, cc = (t & 15) * 4;
    #pragma unroll
    for (int i = 0; i < 16; ++i) {
        int rr = i * 2 + cr;
        *(float4*)&stage[w][rr][cc] =
            *(const float4*)&M[(((srow + rr) * RR) + r) * 64 + cc];
    }
    __syncwarp();

    ull xp[32];
    {
        const ulonglong2* rp = (const ulonglong2*)&stage[w][t][0];
        #pragma unroll
        for (int i = 0; i < 16; ++i) { ulonglong2 v = rp[i]; xp[2 * i] = v.x; xp[2 * i + 1] = v.y; }
    }
    float sum = 0.f, sq = 0.f;
    #pragma unroll
    for (int i = 0; i < 32; ++i) { float2 f = upk(xp[i]); sum += f.x + f.y; sq += f.x * f.x + f.y * f.y; }
    const float mu = sum * (1.f / 64.f);
    const float rstd = rsqrtf(sq * (1.f / 64.f) - mu * mu + 1e-5f);
    const int s = srow + t;
    const float mk = g_maskT[r * SS + s];
    g_stats[(size_t)r * SS + s] = make_float2(mu, rstd);

    #pragma unroll
    for (int c = 0; c < 16; ++c) {
        const ulonglong2* wp_ = (const ulonglong2*)&sAW[c][0];
        ull a0 = 0ull, a1 = 0ull;
        #pragma unroll
        for (int i = 0; i < 16; ++i) {
            ulonglong2 v = wp_[i];
            a0 = ffma2(xp[2 * i], v.x, a0);
            a1 = ffma2(xp[2 * i + 1], v.y, a1);
        }
        float2 f0 = upk(a0), f1 = upk(a1);
        float dot = f0.x + f0.y + f1.x + f1.y;
        g_kv[((r * 16 + c) * SS) + s] = rstd * (dot - mu * sS1[c]) + sbk[c];
    }

    {
        const float mkr = mk * rstd;
        const ull mp = pk2(mkr, mkr);
        float4* qr = (float4*)&stage[w][t][0];
        #pragma unroll
        for (int i = 0; i < 16; ++i) {
            float2 a = upk(ffma2(xp[2 * i], mp, 0ull));
            float2 b = upk(ffma2(xp[2 * i + 1], mp, 0ull));
            qr[i] = make_float4(a.x, a.y, b.x, b.y);
        }
        stage[w][t][64] = mkr * mu;
        stage[w][t][65] = mk;
    }
    __syncwarp();
    {
        float ax = 0.f, ay = 0.f;
        #pragma unroll
        for (int rr = 0; rr < 32; ++rr) {
            float2 v = *(const float2*)&stage[w][rr][2 * t];
            ax += v.x; ay += v.y;
        }
        sQ[w][2 * t] = ax; sQ[w][2 * t + 1] = ay;
        if (t < 2) {
            float e = 0.f;
            #pragma unroll
            for (int rr = 0; rr < 32; ++rr) e += stage[w][rr][64 + t];
            sQ[w][64 + t] = e;
        }
    }
    __syncthreads();
    if (tid < 66) {
        float a = sQ[0][tid] + sQ[1][tid] + sQ[2][tid] + sQ[3][tid];
        g_qpart[(r * 16 + blockIdx.x) * 68 + tid] = a;
    }
}

// ---------------------------------------------------------------------------
// Kernel B: pooled q, two-pass streaming softmax over S (52us version)
// ---------------------------------------------------------------------------
__global__ __launch_bounds__(256) void kernelB(
    const float* __restrict__ Wq, const float* __restrict__ lng,
    const float* __restrict__ lnb)
{
    __shared__ float sqa[68];
    __shared__ float sq[64];
    __shared__ float smax[8];
    __shared__ float red[8][80];
    const int tid = threadIdx.x, w = tid >> 5, t = tid & 31, r = blockIdx.x;

    if (tid < 66) {
        float a = 0.f;
        #pragma unroll
        for (int c = 0; c < 16; ++c) a += g_qpart[(r * 16 + c) * 68 + tid];
        sqa[tid] = a;
    }
    __syncthreads();
    if (tid < 64) {
        float Pmu = sqa[64], Pc = sqa[65];
        sqa[tid] = (lng[tid] * (sqa[tid] - Pmu) + lnb[tid] * Pc) / (Pc + 1e-10f);
    }
    __syncthreads();
    if (tid < 64) {
        float acc = 0.f;
        #pragma unroll
        for (int d = 0; d < 64; ++d) acc += sqa[d] * Wq[d * 64 + tid];
        sq[tid] = acc * 0.35355339059327373f;
    }
    __syncthreads();

    float mx[8];
    #pragma unroll
    for (int h = 0; h < 8; ++h) mx[h] = -3.0e38f;
    for (int s = tid; s < SS; s += 256) {
        float kk[8];
        #pragma unroll
        for (int c = 0; c < 8; ++c) kk[c] = g_kv[((r * 16 + c) * SS) + s];
        float bias = 1e9f * (g_maskT[r * SS + s] - 1.f);
        #pragma unroll
        for (int h = 0; h < 8; ++h) {
            float lg = bias;
            #pragma unroll
            for (int c = 0; c < 8; ++c) lg += sq[h * 8 + c] * kk[c];
            mx[h] = fmaxf(mx[h], lg);
        }
    }
    #pragma unroll
    for (int h = 0; h < 8; ++h) {
        #pragma unroll
        for (int o = 16; o > 0; o >>= 1) mx[h] = fmaxf(mx[h], __shfl_xor_sync(0xffffffffu, mx[h], o));
    }
    if (t < 8) red[w][t] = mx[t];
    __syncthreads();
    if (tid < 8) {
        float m = red[0][tid];
        #pragma unroll
        for (int ww = 1; ww < 8; ++ww) m = fmaxf(m, red[ww][tid]);
        smax[tid] = m;
    }
    __syncthreads();

    float Z[8];
    float acc[64];
    #pragma unroll
    for (int h = 0; h < 8; ++h) Z[h] = 0.f;
    #pragma unroll
    for (int i = 0; i < 64; ++i) acc[i] = 0.f;
    for (int s = tid; s < SS; s += 256) {
        float kk[8], vv[8];
        #pragma unroll
        for (int c = 0; c < 8; ++c) kk[c] = g_kv[((r * 16 + c) * SS) + s];
        #pragma unroll
        for (int c = 0; c < 8; ++c) vv[c] = g_kv[((r * 16 + 8 + c) * SS) + s];
        float bias = 1e9f * (g_maskT[r * SS + s] - 1.f);
        #pragma unroll
        for (int h = 0; h < 8; ++h) {
            float lg = bias;
            #pragma unroll
            for (int c = 0; c < 8; ++c) lg += sq[h * 8 + c] * kk[c];
            float e = __expf(lg - smax[h]);
            Z[h] += e;
            #pragma unroll
            for (int c = 0; c < 8; ++c) acc[h * 8 + c] += e * vv[c];
        }
    }
    #pragma unroll
    for (int i = 0; i < 64; ++i) {
        float v = acc[i];
        #pragma unroll
        for (int o = 16; o > 0; o >>= 1) v += __shfl_xor_sync(0xffffffffu, v, o);
        if (t == 0) red[w][i] = v;
    }
    #pragma unroll
    for (int h = 0; h < 8; ++h) {
        float v = Z[h];
        #pragma unroll
        for (int o = 16; o > 0; o >>= 1) v += __shfl_xor_sync(0xffffffffu, v, o);
        if (t == 0) red[w][64 + h] = v;
    }
    __syncthreads();
    if (tid < 72) {
        float v = 0.f;
        #pragma unroll
        for (int ww = 0; ww < 8; ++ww) v += red[ww][tid];
        red[0][tid] = v;
    }
    __syncthreads();
    if (tid < 64) g_o[r * 64 + tid] = red[0][tid] / red[0][64 + (tid >> 3)];
}

// ---------------------------------------------------------------------------
// Kernel C (warp-MMA tf32, v4): block = fixed r, ONE tile of 128 s-rows.
// Warp owns 32 rows -> B frags amortized over 16 mma per load (2x less B
// traffic). Fully warp-synchronous; B via __ldg (L1-hot).
// ---------------------------------------------------------------------------
__global__ __launch_bounds__(128, 3) void kernelC(
    const float* __restrict__ M, const float* __restrict__ bov,
    float* __restrict__ outp, int sbase)
{
    extern __shared__ __align__(16) float dyn[];
    float* XT = dyn;               // [128][68] exact x
    float* GT = dyn + 128 * 68;    // [128][68] ghat (tf32 bits)
    __shared__ float soo[64], sS1g[64], sbG[64], sbo[64];

    const int tid = threadIdx.x, wid = tid >> 5, lid = tid & 31;
    const int g = lid >> 2, tg = lid & 3;
    const int r = blockIdx.y;
    const int s0 = (sbase + blockIdx.x) * 128;

    if (tid < 64) {
        soo[tid]  = g_o[r * 64 + tid];
        sS1g[tid] = g_S1g[tid];
        sbG[tid]  = g_bG[tid];
        sbo[tid]  = bov[tid];
    }
    __syncthreads();

    const int base = wid * 32;
    // warp-local tile load (warp owns rows [base, base+32))
    #pragma unroll
    for (int it = 0; it < 16; ++it) {
        int f = lid + it * 32;
        int row = base + (f >> 4), c4 = (f & 15) * 4;
        *(float4*)&XT[row * 68 + c4] =
            *(const float4*)&M[(((size_t)(s0 + row)) * RR + r) * 64 + c4];
    }
    __syncwarp();

    const int r0 = base + g;
    const float2 st0 = g_stats[(size_t)r * SS + s0 + r0];
    const float2 st1 = g_stats[(size_t)r * SS + s0 + r0 + 8];
    const float2 st2 = g_stats[(size_t)r * SS + s0 + r0 + 16];
    const float2 st3 = g_stats[(size_t)r * SS + s0 + r0 + 24];

    uint32_t af[8][8];
    #pragma unroll
    for (int k = 0; k < 8; ++k) {
        af[k][0] = f2tf32(XT[r0 * 68 + k * 8 + tg]);
        af[k][1] = f2tf32(XT[(r0 + 8) * 68 + k * 8 + tg]);
        af[k][2] = f2tf32(XT[r0 * 68 + k * 8 + tg + 4]);
        af[k][3] = f2tf32(XT[(r0 + 8) * 68 + k * 8 + tg + 4]);
        af[k][4] = f2tf32(XT[(r0 + 16) * 68 + k * 8 + tg]);
        af[k][5] = f2tf32(XT[(r0 + 24) * 68 + k * 8 + tg]);
        af[k][6] = f2tf32(XT[(r0 + 16) * 68 + k * 8 + tg + 4]);
        af[k][7] = f2tf32(XT[(r0 + 24) * 68 + k * 8 + tg + 4]);
    }
    // ---- GEMM1 + sigmoid gate epilogue -> GT ----
    #pragma unroll
    for (int n = 0; n < 8; ++n) {
        float dl[4] = {0.f, 0.f, 0.f, 0.f};
        float dh[4] = {0.f, 0.f, 0.f, 0.f};
        uint4 q0 = __ldg(&g_BP1[n * 32 + lid]);
        uint4 q1 = __ldg(&g_BP1[256 + n * 32 + lid]);
        uint4 q2 = __ldg(&g_BP1[512 + n * 32 + lid]);
        uint4 q3 = __ldg(&g_BP1[768 + n * 32 + lid]);
        mma_tf32(dl, af[0], q0.x, q0.y);  mma_tf32(dh, af[0] + 4, q0.x, q0.y);
        mma_tf32(dl, af[1], q0.z, q0.w);  mma_tf32(dh, af[1] + 4, q0.z, q0.w);
        mma_tf32(dl, af[2], q1.x, q1.y);  mma_tf32(dh, af[2] + 4, q1.x, q1.y);
        mma_tf32(dl, af[3], q1.z, q1.w);  mma_tf32(dh, af[3] + 4, q1.z, q1.w);
        mma_tf32(dl, af[4], q2.x, q2.y);  mma_tf32(dh, af[4] + 4, q2.x, q2.y);
        mma_tf32(dl, af[5], q2.z, q2.w);  mma_tf32(dh, af[5] + 4, q2.z, q2.w);
        mma_tf32(dl, af[6], q3.x, q3.y);  mma_tf32(dh, af[6] + 4, q3.x, q3.y);
        mma_tf32(dl, af[7], q3.z, q3.w);  mma_tf32(dh, af[7] + 4, q3.z, q3.w);
        const int j0 = n * 8 + 2 * tg;
        const float s1a = sS1g[j0], s1b = sS1g[j0 + 1];
        const float bga = sbG[j0],  bgb = sbG[j0 + 1];
        const float oa  = soo[j0],  ob  = soo[j0 + 1];
        float g00 = oa / (1.f + __expf(-(st0.y * (dl[0] - st0.x * s1a) + bga)));
        float g01 = ob / (1.f + __expf(-(st0.y * (dl[1] - st0.x * s1b) + bgb)));
        float g10 = oa / (1.f + __expf(-(st1.y * (dl[2] - st1.x * s1a) + bga)));
        float g11 = ob / (1.f + __expf(-(st1.y * (dl[3] - st1.x * s1b) + bgb)));
        float g20 = oa / (1.f + __expf(-(st2.y * (dh[0] - st2.x * s1a) + bga)));
        float g21 = ob / (1.f + __expf(-(st2.y * (dh[1] - st2.x * s1b) + bgb)));
        float g30 = oa / (1.f + __expf(-(st3.y * (dh[2] - st3.x * s1a) + bga)));
        float g31 = ob / (1.f + __expf(-(st3.y * (dh[3] - st3.x * s1b) + bgb)));
        *(uint2*)&GT[r0 * 68 + j0]        = make_uint2(f2tf32(g00), f2tf32(g01));
        *(uint2*)&GT[(r0 + 8) * 68 + j0]  = make_uint2(f2tf32(g10), f2tf32(g11));
        *(uint2*)&GT[(r0 + 16) * 68 + j0] = make_uint2(f2tf32(g20), f2tf32(g21));
        *(uint2*)&GT[(r0 + 24) * 68 + j0] = make_uint2(f2tf32(g30), f2tf32(g31));
    }
    __syncwarp();

    // ---- GEMM2 A frags (ghat, already tf32 bits) ----
    {
        const uint32_t* GTu = (const uint32_t*)GT;
        #pragma unroll
        for (int k = 0; k < 8; ++k) {
            af[k][0] = GTu[r0 * 68 + k * 8 + tg];
            af[k][1] = GTu[(r0 + 8) * 68 + k * 8 + tg];
            af[k][2] = GTu[r0 * 68 + k * 8 + tg + 4];
            af[k][3] = GTu[(r0 + 8) * 68 + k * 8 + tg + 4];
            af[k][4] = GTu[(r0 + 16) * 68 + k * 8 + tg];
            af[k][5] = GTu[(r0 + 24) * 68 + k * 8 + tg];
            af[k][6] = GTu[(r0 + 16) * 68 + k * 8 + tg + 4];
            af[k][7] = GTu[(r0 + 24) * 68 + k * 8 + tg + 4];
        }
    }
    __syncwarp();
    // ---- GEMM2 + bias + exact residual -> direct gmem store ----
    float* o0p = &outp[(((size_t)(s0 + r0)) * RR + r) * 64];
    float* o1p = &outp[(((size_t)(s0 + r0 + 8)) * RR + r) * 64];
    float* o2p = &outp[(((size_t)(s0 + r0 + 16)) * RR + r) * 64];
    float* o3p = &outp[(((size_t)(s0 + r0 + 24)) * RR + r) * 64];
    #pragma unroll
    for (int n = 0; n < 8; ++n) {
        float dl[4] = {0.f, 0.f, 0.f, 0.f};
        float dh[4] = {0.f, 0.f, 0.f, 0.f};
        uint4 q0 = __ldg(&g_BP2[n * 32 + lid]);
        uint4 q1 = __ldg(&g_BP2[256 + n * 32 + lid]);
        uint4 q2 = __ldg(&g_BP2[512 + n * 32 + lid]);
        uint4 q3 = __ldg(&g_BP2[768 + n * 32 + lid]);
        mma_tf32(dl, af[0], q0.x, q0.y);  mma_tf32(dh, af[0] + 4, q0.x, q0.y);
        mma_tf32(dl, af[1], q0.z, q0.w);  mma_tf32(dh, af[1] + 4, q0.z, q0.w);
        mma_tf32(dl, af[2], q1.x, q1.y);  mma_tf32(dh, af[2] + 4, q1.x, q1.y);
        mma_tf32(dl, af[3], q1.z, q1.w);  mma_tf32(dh, af[3] + 4, q1.z, q1.w);
        mma_tf32(dl, af[4], q2.x, q2.y);  mma_tf32(dh, af[4] + 4, q2.x, q2.y);
        mma_tf32(dl, af[5], q2.z, q2.w);  mma_tf32(dh, af[5] + 4, q2.z, q2.w);
        mma_tf32(dl, af[6], q3.x, q3.y);  mma_tf32(dh, af[6] + 4, q3.x, q3.y);
        mma_tf32(dl, af[7], q3.z, q3.w);  mma_tf32(dh, af[7] + 4, q3.z, q3.w);
        const int c0 = n * 8 + 2 * tg;
        float2 x0 = *(const float2*)&XT[r0 * 68 + c0];
        float2 x1 = *(const float2*)&XT[(r0 + 8) * 68 + c0];
        float2 x2 = *(const float2*)&XT[(r0 + 16) * 68 + c0];
        float2 x3 = *(const float2*)&XT[(r0 + 24) * 68 + c0];
        *(float2*)&o0p[c0] = make_float2(dl[0] + sbo[c0] + x0.x, dl[1] + sbo[c0 + 1] + x0.y);
        *(float2*)&o1p[c0] = make_float2(dl[2] + sbo[c0] + x1.x, dl[3] + sbo[c0 + 1] + x1.y);
        *(float2*)&o2p[c0] = make_float2(dh[0] + sbo[c0] + x2.x, dh[1] + sbo[c0 + 1] + x2.y);
        *(float2*)&o3p[c0] = make_float2(dh[2] + sbo[c0] + x3.x, dh[3] + sbo[c0 + 1] + x3.y);
    }
}

// ---------------------------------------------------------------------------
extern "C" void kernel_launch(void* const* d_in, const int* in_sizes, int n_in,
                              void* d_out, int out_size)
{
    (void)in_sizes; (void)n_in; (void)out_size;
    const float* M    = (const float*)d_in[0];
    const float* mask = (const float*)d_in[1];
    const float* ln_g = (const float*)d_in[2];
    const float* ln_b = (const float*)d_in[3];
    const float* Wq   = (const float*)d_in[4];
    const float* Wk   = (const float*)d_in[5];
    const float* Wv   = (const float*)d_in[6];
    const float* Wg   = (const float*)d_in[7];
    const float* bg   = (const float*)d_in[8];
    const float* Wo   = (const float*)d_in[9];
    const float* bo   = (const float*)d_in[10];
    float* outp = (float*)d_out;

    const int smemC = 2 * 128 * 68 * 4;  // 69632 B dynamic
    cudaFuncSetAttribute(kernelC, cudaFuncAttributeMaxDynamicSharedMemorySize, smemC);

    kernelDP<<<769, 256>>>(mask, ln_g, ln_b, Wk, Wv, Wg, bg, Wo);
    kernelA<<<dim3(16, 384), 128>>>(M);
    kernelB<<<384, 256>>>(Wq, ln_g, ln_b);
    kernelC<<<dim3(6, 384), 128, smemC>>>(M, bo, outp, 0);
    kernelC<<<dim3(5, 384), 128, smemC>>>(M, bo, outp, 6);
    kernelC<<<dim3(5, 384), 128, smemC>>>(M, bo, outp, 11);
}